// round 10
// baseline (speedup 1.0000x reference)
#include <cuda_runtime.h>

// ---------------------------------------------------------------------------
// EASeq2SeqLSTM: persistent-kernel fp32 implementation.
// B=256, L=365, F=32, S=27, H=256, HOR=24, NT=1.
//
// Grid: 128 CTAs x 256 threads, one CTA per SM, software grid barrier.
// CTA tile: 64 batches x 8 hidden units (x4 gates). Each thread owns
// (1 unit, 2 batches, 4 gates); cell state c stays in registers for the
// whole kernel. Weights live in shared memory per phase; per-step
// activations are staged transposed [k][b] in shared memory.
// ---------------------------------------------------------------------------

namespace {
constexpr int B_   = 256;
constexpr int L_   = 365;
constexpr int F_   = 32;
constexpr int S_   = 27;
constexpr int H_   = 256;
constexpr int HOR_ = 24;
constexpr int HB   = H_ * B_;      // 65536
constexpr int NCTA = 128;
constexpr int NTHR = 256;

// shared memory: weight region + staging region
constexpr int SW_FLOATS = 32 * 260 + 32 * 512;  // 24704 (decoder worst case)
constexpr int SX_FLOATS = 288 * 64;             // 18432 (EA worst case)
constexpr int SMEM_BYTES = (SW_FLOATS + SX_FLOATS) * (int)sizeof(float);
}

// ------------------------- global scratch (no runtime allocation) ----------
__device__ float g_xT[L_ * F_ * B_];            // [t][f][b]
__device__ float g_seqT[(size_t)L_ * H_ * B_];  // [t][u][b]   EA outputs
__device__ float g_hEA[2 * HB];                 // ping-pong [u][b]
__device__ float g_hENC[2 * HB];
__device__ float g_hA[2 * HB];
__device__ float g_hB[2 * HB];
__device__ float g_din[B_];
__device__ unsigned g_cnt;
__device__ volatile unsigned g_gen;

// ------------------------- grid barrier ------------------------------------
// Generation-based; works with any starting generation, so state is
// self-consistent across graph replays (g_cnt returns to 0 every barrier).
__device__ __forceinline__ void grid_sync() {
    __threadfence();            // order this thread's prior global writes
    __syncthreads();            // all threads of CTA done writing
    if (threadIdx.x == 0) {
        unsigned gen = g_gen;
        if (atomicAdd(&g_cnt, 1u) == NCTA - 1u) {
            g_cnt = 0u;
            __threadfence();
            g_gen = gen + 1u;   // volatile store: release
        } else {
            while (g_gen == gen) { }  // volatile read: bypasses L1
        }
        __threadfence();
    }
    __syncthreads();
}

// ------------------------- math helpers ------------------------------------
__device__ __forceinline__ float sigf(float v) {
    return __fdividef(1.f, 1.f + __expf(-v));
}
__device__ __forceinline__ float tanh_(float v) {
    float t = __expf(2.f * v);
    return __fdividef(t - 1.f, t + 1.f);
}

// ------------------------- staging helpers ---------------------------------
// dst[r*64 + b] = src[r*B + b0 + b], float4-vectorized, coalesced.
__device__ __forceinline__ void stage_rows_ld(float* dst, const float* __restrict__ src,
                                              int nrows, int b0) {
    for (int i = threadIdx.x; i < nrows * 16; i += NTHR) {
        int r = i >> 4, b = (i & 15) << 2;
        *reinterpret_cast<float4*>(dst + r * 64 + b) =
            *reinterpret_cast<const float4*>(src + r * B_ + b0 + b);
    }
}
// Same but bypassing L1 (cross-CTA, repeatedly-rewritten buffers).
__device__ __forceinline__ void stage_rows_cg(float* dst, const float* src,
                                              int nrows, int b0) {
    for (int i = threadIdx.x; i < nrows * 16; i += NTHR) {
        int r = i >> 4, b = (i & 15) << 2;
        *reinterpret_cast<float4*>(dst + r * 64 + b) =
            __ldcg(reinterpret_cast<const float4*>(src + r * B_ + b0 + b));
    }
}

// ------------------------- inner GEMV accumulation -------------------------
// a[8] = 4 gates x 2 batches. w0 points at gate-0 row for this thread's unit;
// gate rows are gstride apart. xs is the [k][64] staging buffer; tl = 2*lane.
__device__ __forceinline__ void accum8(float* a, const float* __restrict__ w0,
                                       int gstride, const float* __restrict__ xs,
                                       int K, int tl) {
    const float* wg0 = w0;
    const float* wg1 = w0 + gstride;
    const float* wg2 = w0 + 2 * gstride;
    const float* wg3 = w0 + 3 * gstride;
#pragma unroll 4
    for (int k = 0; k < K; ++k) {
        float2 xv = *reinterpret_cast<const float2*>(xs + k * 64 + tl);
        float w0v = wg0[k], w1v = wg1[k], w2v = wg2[k], w3v = wg3[k];
        a[0] += w0v * xv.x; a[1] += w0v * xv.y;
        a[2] += w1v * xv.x; a[3] += w1v * xv.y;
        a[4] += w2v * xv.x; a[5] += w2v * xv.y;
        a[6] += w3v * xv.x; a[7] += w3v * xv.y;
    }
}

// ---------------------------------------------------------------------------
__global__ void __launch_bounds__(NTHR, 1)
ea_seq2seq_kernel(const float* __restrict__ x,    const float* __restrict__ s,
                  const float* __restrict__ Wf,   const float* __restrict__ bf,
                  const float* __restrict__ Wo,   const float* __restrict__ bo,
                  const float* __restrict__ Wi,   const float* __restrict__ bi,
                  const float* __restrict__ Wg,   const float* __restrict__ bg,
                  const float* __restrict__ Wsi,  const float* __restrict__ bsi,
                  const float* __restrict__ Wsg,  const float* __restrict__ bsg,
                  const float* __restrict__ eWih, const float* __restrict__ eWhh,
                  const float* __restrict__ ebih, const float* __restrict__ ebhh,
                  const float* __restrict__ dWih0, const float* __restrict__ dWhh0,
                  const float* __restrict__ dbih0, const float* __restrict__ dbhh0,
                  const float* __restrict__ dWih1, const float* __restrict__ dWhh1,
                  const float* __restrict__ dbih1, const float* __restrict__ dbhh1,
                  const float* __restrict__ fcW,  const float* __restrict__ fcb,
                  float* __restrict__ out)
{
    extern __shared__ float smem[];
    float* sW = smem;                 // weights
    float* sX = smem + SW_FLOATS;     // [k][64] staged activations

    const int tid  = threadIdx.x;
    const int bt   = blockIdx.x & 3;   // batch tile  [0,4)
    const int ut   = blockIdx.x >> 2;  // unit tile   [0,32)
    const int b0   = bt * 64;
    const int u0   = ut * 8;
    const int ul   = tid >> 5;         // warp id = local unit
    const int lane = tid & 31;
    const int tl   = lane * 2;         // local batch pair
    const int ug   = u0 + ul;          // global unit
    const int gb   = b0 + tl;          // global batch (pair base)

    // ---------------- phase 0: transpose x, zero din ----------------------
    {
        int gt = blockIdx.x * NTHR + tid;
        for (int i = gt; i < L_ * F_ * B_; i += NCTA * NTHR) {
            int t = i / (F_ * B_);
            int r = i - t * (F_ * B_);
            int f = r >> 8;        // / B_
            int b = r & 255;       // % B_
            g_xT[i] = x[(size_t)b * (L_ * F_) + t * F_ + f];
        }
        if (blockIdx.x == 0) g_din[tid] = 0.f;
    }

    // static contributions si/sg (include bsi/bsg), per-thread registers
    float si0, si1, sg0, sg1;
    {
        si0 = si1 = bsi[ug];
        sg0 = sg1 = bsg[ug];
#pragma unroll
        for (int j = 0; j < S_; ++j) {
            float wiv = Wsi[ug * S_ + j];
            float wgv = Wsg[ug * S_ + j];
            float sv0 = s[(gb)     * S_ + j];
            float sv1 = s[(gb + 1) * S_ + j];
            si0 += wiv * sv0; si1 += wiv * sv1;
            sg0 += wgv * sv0; sg1 += wgv * sv1;
        }
    }

    // EA weights -> smem, gate order f,o,i,g ; row length 288
    {
        const float* Ws[4] = {Wf, Wo, Wi, Wg};
        for (int i = tid; i < 4 * 8 * 288; i += NTHR) {
            int g = i / (8 * 288);
            int r = i - g * (8 * 288);
            int u = r / 288;
            int k = r - u * 288;
            sW[i] = Ws[g][(u0 + u) * 288 + k];
        }
    }
    const float bF = bf[ug], bO = bo[ug], bI = bi[ug], bG = bg[ug];

    grid_sync();   // x transpose + din visible; smem weights via its syncthreads

    // ---------------- phase 1: EA-LSTM over L steps ------------------------
    float c0 = 0.f, c1 = 0.f;
    int p = 0;
    for (int t = 0; t < L_; ++t) {
        stage_rows_ld(sX, g_xT + t * F_ * B_, F_, b0);         // rows 0..31: x_t
        if (t == 0) {
            for (int i = tid; i < H_ * 64; i += NTHR) sX[F_ * 64 + i] = 0.f;
        } else {
            stage_rows_cg(sX + F_ * 64, g_hEA + p * HB, H_, b0); // rows 32..287: h
        }
        __syncthreads();

        float a[8] = {bF, bF, bO, bO, bI + si0, bI + si1, bG + sg0, bG + sg1};
        accum8(a, sW + ul * 288, 8 * 288, sX, 288, tl);

        float f0 = sigf(a[0]), f1 = sigf(a[1]);
        float o0 = sigf(a[2]), o1 = sigf(a[3]);
        float i0 = sigf(a[4]), i1 = sigf(a[5]);
        float q0 = tanh_(a[6]), q1 = tanh_(a[7]);
        c0 = f0 * c0 + i0 * q0;
        c1 = f1 * c1 + i1 * q1;
        float2 hv = make_float2(o0 * tanh_(c0), o1 * tanh_(c1));

        *reinterpret_cast<float2*>(g_hEA + (1 - p) * HB + ug * B_ + gb) = hv;
        *reinterpret_cast<float2*>(g_seqT + (size_t)t * HB + ug * B_ + gb) = hv;
        if (t == L_ - 1)
            *reinterpret_cast<float2*>(g_hENC + ug * B_ + gb) = hv;  // enc init h
        p ^= 1;
        grid_sync();
    }

    // ---------------- phase 2: encoder LSTM (gate order i,f,g,o) -----------
    for (int i = tid; i < 4 * 8 * 512; i += NTHR) {
        int g = i / (8 * 512);
        int r = i - g * (8 * 512);
        int u = r >> 9;
        int k = r & 511;
        int go = g * H_ + u0 + u;
        sW[i] = (k < 256) ? eWih[go * H_ + k] : eWhh[go * H_ + (k - 256)];
    }
    const float ebI = ebih[0 * H_ + ug] + ebhh[0 * H_ + ug];
    const float ebF = ebih[1 * H_ + ug] + ebhh[1 * H_ + ug];
    const float ebG = ebih[2 * H_ + ug] + ebhh[2 * H_ + ug];
    const float ebO = ebih[3 * H_ + ug] + ebhh[3 * H_ + ug];
    __syncthreads();

    p = 0;   // encoder c inherits EA final c in registers (c0,c1)
    for (int t = 0; t < L_; ++t) {
        float a[8] = {ebI, ebI, ebF, ebF, ebG, ebG, ebO, ebO};

        stage_rows_ld(sX, g_seqT + (size_t)t * HB, H_, b0);   // xt = ea_seq[t]
        __syncthreads();
        accum8(a, sW + ul * 512, 8 * 512, sX, 256, tl);
        __syncthreads();
        stage_rows_cg(sX, g_hENC + p * HB, H_, b0);           // recurrent h
        __syncthreads();
        accum8(a, sW + ul * 512 + 256, 8 * 512, sX, 256, tl);

        float ii0 = sigf(a[0]), ii1 = sigf(a[1]);
        float ff0 = sigf(a[2]), ff1 = sigf(a[3]);
        float qg0 = tanh_(a[4]), qg1 = tanh_(a[5]);
        float oo0 = sigf(a[6]), oo1 = sigf(a[7]);
        c0 = ff0 * c0 + ii0 * qg0;
        c1 = ff1 * c1 + ii1 * qg1;
        float2 hv = make_float2(oo0 * tanh_(c0), oo1 * tanh_(c1));

        *reinterpret_cast<float2*>(g_hENC + (1 - p) * HB + ug * B_ + gb) = hv;
        if (t == L_ - 1) {
            *reinterpret_cast<float2*>(g_hA + ug * B_ + gb) = hv;  // dec init
            *reinterpret_cast<float2*>(g_hB + ug * B_ + gb) = hv;
        }
        p ^= 1;
        grid_sync();
    }

    // ---------------- phase 3: decoder (2-layer, 24 steps) -----------------
    // layer0 rows: stride 260 (col0 = Wih0 scalar, 1..256 = Whh0, pad)
    for (int i = tid; i < 32 * 260; i += NTHR) {
        int row = i / 260;
        int k   = i - row * 260;
        int g = row >> 3, u = row & 7;
        int go = g * H_ + u0 + u;
        float v = 0.f;
        if (k == 0)        v = dWih0[go];
        else if (k <= 256) v = dWhh0[go * H_ + (k - 1)];
        sW[i] = v;
    }
    // layer1 rows: 512 = Wih1 || Whh1, at offset 8320
    for (int i = tid; i < 32 * 512; i += NTHR) {
        int row = i >> 9;
        int k   = i & 511;
        int g = row >> 3, u = row & 7;
        int go = g * H_ + u0 + u;
        sW[8320 + i] = (k < 256) ? dWih1[go * H_ + k] : dWhh1[go * H_ + (k - 256)];
    }
    const float d0I = dbih0[0*H_+ug] + dbhh0[0*H_+ug];
    const float d0F = dbih0[1*H_+ug] + dbhh0[1*H_+ug];
    const float d0G = dbih0[2*H_+ug] + dbhh0[2*H_+ug];
    const float d0O = dbih0[3*H_+ug] + dbhh0[3*H_+ug];
    const float d1I = dbih1[0*H_+ug] + dbhh1[0*H_+ug];
    const float d1F = dbih1[1*H_+ug] + dbhh1[1*H_+ug];
    const float d1G = dbih1[2*H_+ug] + dbhh1[2*H_+ug];
    const float d1O = dbih1[3*H_+ug] + dbhh1[3*H_+ug];
    const float fcb0 = fcb[0];
    float cA0 = c0, cA1 = c1, cB0 = c0, cB1 = c1;   // both layers from enc state
    __syncthreads();

    p = 0;
    for (int st = 0; st < HOR_; ++st) {
        // ---- layer 0: xh = [din(1) | hA(256)], K=257 ----
        if (tid < 64) sX[tid] = __ldcg(&g_din[b0 + tid]);
        stage_rows_cg(sX + 64, g_hA + p * HB, H_, b0);
        __syncthreads();
        {
            float a[8] = {d0I, d0I, d0F, d0F, d0G, d0G, d0O, d0O};
            accum8(a, sW + ul * 260, 8 * 260, sX, 257, tl);
            float ii0 = sigf(a[0]), ii1 = sigf(a[1]);
            float ff0 = sigf(a[2]), ff1 = sigf(a[3]);
            float qg0 = tanh_(a[4]), qg1 = tanh_(a[5]);
            float oo0 = sigf(a[6]), oo1 = sigf(a[7]);
            cA0 = ff0 * cA0 + ii0 * qg0;
            cA1 = ff1 * cA1 + ii1 * qg1;
            float2 hv = make_float2(oo0 * tanh_(cA0), oo1 * tanh_(cA1));
            *reinterpret_cast<float2*>(g_hA + (1 - p) * HB + ug * B_ + gb) = hv;
        }
        grid_sync();

        // ---- layer 1: xh = [hA_new(256) | hB(256)], K=512 ----
        {
            float a[8] = {d1I, d1I, d1F, d1F, d1G, d1G, d1O, d1O};
            stage_rows_cg(sX, g_hA + (1 - p) * HB, H_, b0);
            __syncthreads();
            accum8(a, sW + 8320 + ul * 512, 8 * 512, sX, 256, tl);
            __syncthreads();
            stage_rows_cg(sX, g_hB + p * HB, H_, b0);
            __syncthreads();
            accum8(a, sW + 8320 + ul * 512 + 256, 8 * 512, sX, 256, tl);
            float ii0 = sigf(a[0]), ii1 = sigf(a[1]);
            float ff0 = sigf(a[2]), ff1 = sigf(a[3]);
            float qg0 = tanh_(a[4]), qg1 = tanh_(a[5]);
            float oo0 = sigf(a[6]), oo1 = sigf(a[7]);
            cB0 = ff0 * cB0 + ii0 * qg0;
            cB1 = ff1 * cB1 + ii1 * qg1;
            float2 hv = make_float2(oo0 * tanh_(cB0), oo1 * tanh_(cB1));
            *reinterpret_cast<float2*>(g_hB + (1 - p) * HB + ug * B_ + gb) = hv;
        }
        grid_sync();

        // ---- output head: pred = hB @ fcW + fcb; feeds next din ----
        if (ut == 0) {   // 4 CTAs (one per batch tile), 4 threads per batch
            int bloc = tid >> 2, q = tid & 3;
            int gb2 = b0 + bloc;
            const float* hb = g_hB + (1 - p) * HB;
            float v = 0.f;
#pragma unroll 4
            for (int k = q * 64; k < q * 64 + 64; ++k)
                v += __ldcg(&hb[k * B_ + gb2]) * fcW[k];
            v += __shfl_xor_sync(0xffffffffu, v, 1);
            v += __shfl_xor_sync(0xffffffffu, v, 2);
            if (q == 0) {
                float pr = v + fcb0;
                out[gb2 * HOR_ + st] = pr;
                g_din[gb2] = pr;
            }
        }
        p ^= 1;
        grid_sync();
    }
}

// ---------------------------------------------------------------------------
extern "C" void kernel_launch(void* const* d_in, const int* in_sizes, int n_in,
                              void* d_out, int out_size) {
    (void)in_sizes; (void)n_in; (void)out_size;
    const float* x     = (const float*)d_in[0];
    const float* s     = (const float*)d_in[1];
    const float* Wf    = (const float*)d_in[2];
    const float* bf    = (const float*)d_in[3];
    const float* Wo    = (const float*)d_in[4];
    const float* bo    = (const float*)d_in[5];
    const float* Wi    = (const float*)d_in[6];
    const float* bi    = (const float*)d_in[7];
    const float* Wg    = (const float*)d_in[8];
    const float* bg    = (const float*)d_in[9];
    const float* Wsi   = (const float*)d_in[10];
    const float* bsi   = (const float*)d_in[11];
    const float* Wsg   = (const float*)d_in[12];
    const float* bsg   = (const float*)d_in[13];
    const float* eWih  = (const float*)d_in[14];
    const float* eWhh  = (const float*)d_in[15];
    const float* ebih  = (const float*)d_in[16];
    const float* ebhh  = (const float*)d_in[17];
    const float* dWih0 = (const float*)d_in[18];
    const float* dWhh0 = (const float*)d_in[19];
    const float* dbih0 = (const float*)d_in[20];
    const float* dbhh0 = (const float*)d_in[21];
    const float* dWih1 = (const float*)d_in[22];
    const float* dWhh1 = (const float*)d_in[23];
    const float* dbih1 = (const float*)d_in[24];
    const float* dbhh1 = (const float*)d_in[25];
    const float* fcW   = (const float*)d_in[26];
    const float* fcb   = (const float*)d_in[27];

    cudaFuncSetAttribute(ea_seq2seq_kernel,
                         cudaFuncAttributeMaxDynamicSharedMemorySize, SMEM_BYTES);
    ea_seq2seq_kernel<<<NCTA, NTHR, SMEM_BYTES>>>(
        x, s, Wf, bf, Wo, bo, Wi, bi, Wg, bg, Wsi, bsi, Wsg, bsg,
        eWih, eWhh, ebih, ebhh,
        dWih0, dWhh0, dbih0, dbhh0, dWih1, dWhh1, dbih1, dbhh1,
        fcW, fcb, (float*)d_out);
}